// round 5
// baseline (speedup 1.0000x reference)
#include <cuda_runtime.h>
#include <math.h>

#define Bc   8
#define Cc   48
#define Nn   4096
#define KK   9
#define NBc  32768          // B*N
#define Ec   (Bc*Nn*KK)     // 294912

// -------- scratch (static device globals; no allocation) --------
__device__ float g_xnT[Bc*Cc*Nn];   // normalized features, CHANNEL-major [b][c][n]
__device__ float g_nodes[NBc*Cc];   // raw features, node-major
__device__ float g_sq[NBc];         // sum of squares of normalized row
__device__ int   g_nn[NBc*KK];      // knn indices (within batch, 0..N-1)
__device__ int   g_deg[NBc];
__device__ float g_dinv[NBc];
__device__ float g_tx1[NBc*Cc];

// faithful replication of jnp.linspace(0, 8, E).astype(int32):
// value_i = fl(fl(i) * fl(8/294911)), truncated toward zero.
__device__ __forceinline__ int edge_count(int i) {
    const float STEP = 8.0f / 294911.0f;
    return (int)((float)i * STEP);
}

// monotone float->uint map: preserves < ordering for all finite floats
__device__ __forceinline__ unsigned int fmono(float d) {
    unsigned int u = __float_as_uint(d);
    return (u & 0x80000000u) ? ~u : (u | 0x80000000u);
}
__device__ __forceinline__ float fmono_inv(unsigned int u) {
    return __uint_as_float((u & 0x80000000u) ? (u ^ 0x80000000u) : ~u);
}

// ---------------- prep: normalize; emit channel-major + node-major ----------------
__global__ void prep_kernel(const float* __restrict__ x) {
    int node = blockIdx.x * blockDim.x + threadIdx.x;
    if (node >= NBc) return;
    int b = node >> 12, n = node & (Nn - 1);
    const float* xb = x + (size_t)b * Cc * Nn + n;
    float v[Cc];
    float ss = 0.f;
#pragma unroll
    for (int c = 0; c < Cc; c++) { v[c] = xb[c * Nn]; ss += v[c] * v[c]; }
    float m = fmaxf(sqrtf(ss), 1e-12f);
    float sq = 0.f;
    float* xT = g_xnT + (size_t)b * Cc * Nn + n;
#pragma unroll
    for (int c = 0; c < Cc; c++) {
        float xv = v[c] / m;
        xT[c * Nn]             = xv;   // channel-major (coalesced across threads)
        g_nodes[node * Cc + c] = v[c];
        sq += xv * xv;
    }
    g_sq[node]  = sq;
    g_deg[node] = 0;
}

// ---------------- KNN: tiled distances + fused top-9 ----------------
// 128 threads/CTA. Each thread: 4 query rows x 8 candidate cols.
// QT=64 query rows per block, MT=64 candidate tile. Tiles are k-major by
// construction (g_xnT is channel-major) -> no transpose, no conflicts.
#define QT 64
#define MT 64

__global__ __launch_bounds__(128, 5) void knn_kernel() {
    __shared__ float qs[Cc * QT];   // qs[k*QT + r]   12 KB
    __shared__ float ms[Cc * MT];   // ms[k*MT + c]   12 KB
    __shared__ float sqs[QT];
    __shared__ float sqm[MT];

    int t    = threadIdx.x;
    int r0   = (t >> 3) * 4;      // 0,4,...,60
    int c0   = (t & 7) * 8;       // 0,8,...,56
    int b    = blockIdx.y;
    int qBase = blockIdx.x * QT;
    int nodeBase = b * Nn;
    const float* xT = g_xnT + (size_t)b * Cc * Nn;

    // load query tile: straight coalesced copy (already k-major)
    for (int i = t; i < Cc * QT / 4; i += 128) {
        int k = i >> 4, c4 = i & 15;
        float4 f = *(const float4*)&xT[k * Nn + qBase + c4 * 4];
        *(float4*)&qs[k * QT + c4 * 4] = f;
    }
    if (t < QT) sqs[t] = g_sq[nodeBase + qBase + t];
    __syncthreads();

    float sqq[4];
#pragma unroll
    for (int r = 0; r < 4; r++) sqq[r] = sqs[r0 + r];

    // top-9 lists: local-memory resident (dynamic indexing), thresholds in regs
    unsigned long long lst[4][KK];
#pragma unroll 1
    for (int r = 0; r < 4; r++)
#pragma unroll 1
        for (int s = 0; s < KK; s++) lst[r][s] = 0xFF800000FFFFFFFFULL;
    float thr[4];
#pragma unroll
    for (int r = 0; r < 4; r++) thr[r] = __int_as_float(0x7F800000);

    for (int mb = 0; mb < Nn; mb += MT) {
        __syncthreads();
        for (int i = t; i < Cc * MT / 4; i += 128) {
            int k = i >> 4, c4 = i & 15;
            float4 f = *(const float4*)&xT[k * Nn + mb + c4 * 4];
            *(float4*)&ms[k * MT + c4 * 4] = f;
        }
        if (t < MT) sqm[t] = g_sq[nodeBase + mb + t];
        __syncthreads();

        float a[4][8];
#pragma unroll
        for (int r = 0; r < 4; r++)
#pragma unroll
            for (int j = 0; j < 8; j++) a[r][j] = 0.f;

#pragma unroll 4
        for (int k = 0; k < Cc; k++) {
            float4 q4 = *(const float4*)&qs[k * QT + r0];
            float4 m0 = *(const float4*)&ms[k * MT + c0];
            float4 m1 = *(const float4*)&ms[k * MT + c0 + 4];
            float qv[4] = {q4.x, q4.y, q4.z, q4.w};
            float mv[8] = {m0.x, m0.y, m0.z, m0.w, m1.x, m1.y, m1.z, m1.w};
#pragma unroll
            for (int r = 0; r < 4; r++)
#pragma unroll
                for (int j = 0; j < 8; j++)
                    a[r][j] = fmaf(qv[r], mv[j], a[r][j]);
        }

#pragma unroll
        for (int r = 0; r < 4; r++)
#pragma unroll
            for (int j = 0; j < 8; j++) {
                float d = (sqq[r] + sqm[c0 + j]) - 2.f * a[r][j];
                if (d <= thr[r]) {
                    unsigned long long key =
                        ((unsigned long long)fmono(d) << 32) |
                        (unsigned int)(mb + c0 + j);
                    if (key < lst[r][KK - 1]) {
                        lst[r][KK - 1] = key;
#pragma unroll 1
                        for (int s = KK - 1; s > 0; --s) {
                            if (lst[r][s] < lst[r][s - 1]) {
                                unsigned long long tmp = lst[r][s];
                                lst[r][s] = lst[r][s - 1]; lst[r][s - 1] = tmp;
                            } else break;
                        }
                        thr[r] = fmono_inv((unsigned int)(lst[r][KK - 1] >> 32));
                    }
                }
            }
    }

    // butterfly merge across the 8 threads (cgrp) sharing these 4 rows
#pragma unroll
    for (int dlt = 1; dlt <= 4; dlt <<= 1) {
#pragma unroll
        for (int r = 0; r < 4; r++) {
            unsigned long long oth[KK];
#pragma unroll
            for (int s = 0; s < KK; s++)
                oth[s] = __shfl_xor_sync(0xffffffffu, lst[r][s], dlt);
#pragma unroll 1
            for (int s = 0; s < KK; s++) {
                if (oth[s] < lst[r][KK - 1]) {
                    lst[r][KK - 1] = oth[s];
#pragma unroll 1
                    for (int s2 = KK - 1; s2 > 0; --s2) {
                        if (lst[r][s2] < lst[r][s2 - 1]) {
                            unsigned long long tmp = lst[r][s2];
                            lst[r][s2] = lst[r][s2 - 1]; lst[r][s2 - 1] = tmp;
                        } else break;
                    }
                }
            }
        }
    }

    if ((t & 7) == 0) {
#pragma unroll
        for (int r = 0; r < 4; r++) {
            int nrow = nodeBase + qBase + r0 + r;
#pragma unroll 1
            for (int s = 0; s < KK; s++)
                g_nn[nrow * KK + s] = (int)(unsigned int)(lst[r][s] & 0xFFFFFFFFu);
        }
    }
}

// ---------------- degree (int atomics: deterministic) ----------------
__global__ void deg_kernel() {
    int i = blockIdx.x * blockDim.x + threadIdx.x;
    if (i >= Ec) return;
    int cnt  = edge_count(i);
    int rown = i / KK;              // b*N + n
    int n    = rown & (Nn - 1);
    int m    = g_nn[i];
    int src  = m + cnt * Nn;
    int dst  = n + cnt * Nn;
    if (src < NBc && dst < NBc) atomicAdd(&g_deg[src], 1);
}

__global__ void dinv_kernel() {
    int i = blockIdx.x * blockDim.x + threadIdx.x;
    if (i >= NBc) return;
    int d = g_deg[i];
    g_dinv[i] = (d > 0) ? (1.0f / sqrtf((float)d)) : 0.0f;
}

// ---------------- Tx1: deterministic gather-side aggregation ----------------
// dst = q*N + n receives only from center rows (b', n) with b' in {q-1, q}
// whose edge index i has count(i)==q (linspace-count structure).
__global__ void tx1_kernel() {
    int flat = blockIdx.x * blockDim.x + threadIdx.x;
    if (flat >= NBc * Cc) return;
    int d  = flat / Cc, ch = flat % Cc;
    int q  = d >> 12, n = d & (Nn - 1);
    float dv = g_dinv[d];
    float acc = 0.f;
#pragma unroll
    for (int bb = 0; bb < 2; bb++) {
        int bp = q - 1 + bb;
        if (bp < 0 || bp >= Bc) continue;
        int ibase = (bp * Nn + n) * KK;
#pragma unroll
        for (int j = 0; j < KK; j++) {
            int i = ibase + j;
            if (edge_count(i) == q) {
                int src = g_nn[i] + q * Nn;   // always < NB since q <= 7
                acc = fmaf(-dv * g_dinv[src], g_nodes[src * Cc + ch], acc);
            }
        }
    }
    g_tx1[flat] = acc;
}

// ---------------- epilogue: out = nodes@W0 + Tx1@W1 + bias ----------------
__global__ void out_kernel(const float* __restrict__ W0, const float* __restrict__ W1,
                           const float* __restrict__ bias, float* __restrict__ out) {
    __shared__ float sW0[Cc * Cc], sW1[Cc * Cc], sb[Cc];
    int t = threadIdx.x;
    for (int i = t; i < Cc * Cc; i += blockDim.x) { sW0[i] = W0[i]; sW1[i] = W1[i]; }
    if (t < Cc) sb[t] = bias[t];
    __syncthreads();
    int flat = blockIdx.x * blockDim.x + t;
    if (flat >= NBc * Cc) return;
    int d = flat / Cc, co = flat % Cc;
    const float* nrow = &g_nodes[d * Cc];
    const float* trow = &g_tx1[d * Cc];
    float acc = sb[co];
#pragma unroll
    for (int k = 0; k < Cc; k++)
        acc = fmaf(nrow[k], sW0[k * Cc + co], fmaf(trow[k], sW1[k * Cc + co], acc));
    out[flat] = acc;
}

// ---------------- launch ----------------
extern "C" void kernel_launch(void* const* d_in, const int* in_sizes, int n_in,
                              void* d_out, int out_size) {
    const float* x    = (const float*)d_in[0];
    const float* W0   = (const float*)d_in[1];
    const float* W1   = (const float*)d_in[2];
    const float* bias = (const float*)d_in[3];
    float* out = (float*)d_out;
    (void)in_sizes; (void)n_in; (void)out_size;

    prep_kernel<<<NBc / 256, 256>>>(x);
    dim3 gknn(Nn / QT, Bc);
    knn_kernel<<<gknn, 128>>>();
    deg_kernel<<<(Ec + 255) / 256, 256>>>();
    dinv_kernel<<<NBc / 256, 256>>>();
    tx1_kernel<<<(NBc * Cc) / 256, 256>>>();
    out_kernel<<<(NBc * Cc) / 256, 256>>>(W0, W1, bias, out);
}

// round 6
// speedup vs baseline: 2.3986x; 2.3986x over previous
#include <cuda_runtime.h>
#include <math.h>

#define Bc   8
#define Cc   48
#define Nn   4096
#define KK   9
#define NBc  32768          // B*N
#define Ec   (Bc*Nn*KK)     // 294912

// -------- scratch (static device globals; no allocation) --------
__device__ float g_xnT[Bc*Cc*Nn];   // normalized features, CHANNEL-major [b][c][n]
__device__ float g_nodes[NBc*Cc];   // raw features, node-major
__device__ float g_sq[NBc];         // sum of squares of normalized row
__device__ int   g_nn[NBc*KK];      // knn indices (within batch, 0..N-1)
__device__ int   g_deg[NBc];
__device__ float g_dinv[NBc];
__device__ float g_tx1[NBc*Cc];

// faithful replication of jnp.linspace(0, 8, E).astype(int32):
// value_i = fl(fl(i) * fl(8/294911)), truncated toward zero.
__device__ __forceinline__ int edge_count(int i) {
    const float STEP = 8.0f / 294911.0f;
    return (int)((float)i * STEP);
}

// monotone float->uint map: preserves < ordering for all finite floats
__device__ __forceinline__ unsigned int fmono(float d) {
    unsigned int u = __float_as_uint(d);
    return (u & 0x80000000u) ? ~u : (u | 0x80000000u);
}
__device__ __forceinline__ float fmono_inv(unsigned int u) {
    return __uint_as_float((u & 0x80000000u) ? (u ^ 0x80000000u) : ~u);
}

// ---------------- prep: normalize; emit channel-major + node-major ----------------
__global__ void prep_kernel(const float* __restrict__ x) {
    int node = blockIdx.x * blockDim.x + threadIdx.x;
    if (node >= NBc) return;
    int b = node >> 12, n = node & (Nn - 1);
    const float* xb = x + (size_t)b * Cc * Nn + n;
    float v[Cc];
    float ss = 0.f;
#pragma unroll
    for (int c = 0; c < Cc; c++) { v[c] = xb[c * Nn]; ss += v[c] * v[c]; }
    float m = fmaxf(sqrtf(ss), 1e-12f);
    float sq = 0.f;
    float* xT = g_xnT + (size_t)b * Cc * Nn + n;
#pragma unroll
    for (int c = 0; c < Cc; c++) {
        float xv = v[c] / m;
        xT[c * Nn]             = xv;   // channel-major (coalesced across threads)
        g_nodes[node * Cc + c] = v[c];
        sq += xv * xv;
    }
    g_sq[node]  = sq;
    g_deg[node] = 0;
}

// ---------------- KNN: tiled distances + fused top-9 (u64 reg lists) ----------------
// Block 256 = round-4 proven mapping: each thread owns 1 query row x 16 cand cols.
// ms tiles are granule-permuted so each m LDS.128 hits one contiguous 64B window.
#define QT 64
#define MT 64

__global__ __launch_bounds__(256, 4) void knn_kernel() {
    __shared__ float qs[Cc * QT];        // [k*64 + r]                (12 KB)
    __shared__ float ms[2][Cc * MT];     // [k*64 + perm(c)] ping-pong (24 KB)
    __shared__ float sqm[2][MT];

    int t    = threadIdx.x;
    int row  = t >> 2;            // 0..63
    int cs   = t & 3;             // column segment 0..3
    int cseg = cs * 16;
    int b    = blockIdx.y;
    int qBase = blockIdx.x * QT;
    int nodeBase = b * Nn;
    const float* xT = g_xnT + (size_t)b * Cc * Nn;

    // qs: straight coalesced copy (already k-major)
    for (int i = t; i < Cc * 16; i += 256) {
        int k = i >> 4, c4 = i & 15;
        *(float4*)&qs[k * QT + c4 * 4] =
            *(const float4*)&xT[k * Nn + qBase + c4 * 4];
    }
    // preload tile 0 with granule permutation:
    // source float4 #c4 (cols c4*4..c4*4+3) -> dest float offset (c4&3)*16+(c4>>2)*4
    for (int i = t; i < Cc * 16; i += 256) {
        int k = i >> 4, c4 = i & 15;
        int dp = ((c4 & 3) << 4) + ((c4 >> 2) << 2);
        *(float4*)&ms[0][k * MT + dp] =
            *(const float4*)&xT[k * Nn + c4 * 4];
    }
    if (t < MT) sqm[0][t] = g_sq[nodeBase + t];
    float sqq = g_sq[nodeBase + qBase + row];

    // sentinel: (d=+INF, idx=0xFFFFFFFF)
    unsigned long long lst[KK];
#pragma unroll
    for (int s = 0; s < KK; s++) lst[s] = 0xFF800000FFFFFFFFULL;
    float thr = __int_as_float(0x7F800000);   // +INF

    __syncthreads();

    int p = 0;
    for (int mb = 0; mb < Nn; mb += MT) {
        // prefetch next tile into the other buffer (overlapped with compute below
        // via the other CTAs; consumed only after the sync at loop end)
        if (mb + MT < Nn) {
            for (int i = t; i < Cc * 16; i += 256) {
                int k = i >> 4, c4 = i & 15;
                int dp = ((c4 & 3) << 4) + ((c4 >> 2) << 2);
                *(float4*)&ms[1 - p][k * MT + dp] =
                    *(const float4*)&xT[k * Nn + (mb + MT) + c4 * 4];
            }
            if (t < MT) sqm[1 - p][t] = g_sq[nodeBase + mb + MT + t];
        }

        const float* msp = ms[p];
        float acc[16];
#pragma unroll
        for (int j = 0; j < 16; j++) acc[j] = 0.f;

#pragma unroll 8
        for (int k = 0; k < Cc; k++) {
            float  qv = qs[k * QT + row];
            const float* mrow = &msp[k * MT + cs * 4];
            // granule g at float offset g*16 + cs*4 -> columns cseg+4g..cseg+4g+3
            float4 m0 = *(const float4*)(mrow + 0);
            float4 m1 = *(const float4*)(mrow + 16);
            float4 m2 = *(const float4*)(mrow + 32);
            float4 m3 = *(const float4*)(mrow + 48);
            acc[0]  = fmaf(qv, m0.x, acc[0]);  acc[1]  = fmaf(qv, m0.y, acc[1]);
            acc[2]  = fmaf(qv, m0.z, acc[2]);  acc[3]  = fmaf(qv, m0.w, acc[3]);
            acc[4]  = fmaf(qv, m1.x, acc[4]);  acc[5]  = fmaf(qv, m1.y, acc[5]);
            acc[6]  = fmaf(qv, m1.z, acc[6]);  acc[7]  = fmaf(qv, m1.w, acc[7]);
            acc[8]  = fmaf(qv, m2.x, acc[8]);  acc[9]  = fmaf(qv, m2.y, acc[9]);
            acc[10] = fmaf(qv, m2.z, acc[10]); acc[11] = fmaf(qv, m2.w, acc[11]);
            acc[12] = fmaf(qv, m3.x, acc[12]); acc[13] = fmaf(qv, m3.y, acc[13]);
            acc[14] = fmaf(qv, m3.z, acc[14]); acc[15] = fmaf(qv, m3.w, acc[15]);
        }

#pragma unroll
        for (int j = 0; j < 16; j++) {
            float d = (sqq + sqm[p][cseg + j]) - 2.f * acc[j];
            if (d <= thr) {
                int mi = mb + cseg + j;
                unsigned long long key =
                    ((unsigned long long)fmono(d) << 32) | (unsigned int)mi;
                if (key < lst[KK - 1]) {
                    lst[KK - 1] = key;
#pragma unroll
                    for (int s = KK - 1; s > 0; --s) {
                        if (lst[s] < lst[s - 1]) {
                            unsigned long long tmp = lst[s];
                            lst[s] = lst[s - 1]; lst[s - 1] = tmp;
                        }
                    }
                    thr = fmono_inv((unsigned int)(lst[KK - 1] >> 32));
                }
            }
        }

        __syncthreads();
        p ^= 1;
    }

    // butterfly merge across the 4 threads (quad) sharing this query row
#pragma unroll
    for (int delta = 1; delta <= 2; delta <<= 1) {
        unsigned long long other[KK];
#pragma unroll
        for (int s = 0; s < KK; s++)
            other[s] = __shfl_xor_sync(0xffffffffu, lst[s], delta);
#pragma unroll
        for (int s = 0; s < KK; s++) {
            if (other[s] < lst[KK - 1]) {
                lst[KK - 1] = other[s];
#pragma unroll
                for (int s2 = KK - 1; s2 > 0; --s2) {
                    if (lst[s2] < lst[s2 - 1]) {
                        unsigned long long tmp = lst[s2];
                        lst[s2] = lst[s2 - 1]; lst[s2 - 1] = tmp;
                    }
                }
            }
        }
    }

    if ((t & 3) == 0) {
        int nrow = nodeBase + qBase + row;
#pragma unroll
        for (int s = 0; s < KK; s++)
            g_nn[nrow * KK + s] = (int)(unsigned int)(lst[s] & 0xFFFFFFFFu);
    }
}

// ---------------- degree (int atomics: deterministic) ----------------
__global__ void deg_kernel() {
    int i = blockIdx.x * blockDim.x + threadIdx.x;
    if (i >= Ec) return;
    int cnt  = edge_count(i);
    int rown = i / KK;              // b*N + n
    int n    = rown & (Nn - 1);
    int m    = g_nn[i];
    int src  = m + cnt * Nn;
    int dst  = n + cnt * Nn;
    if (src < NBc && dst < NBc) atomicAdd(&g_deg[src], 1);
}

__global__ void dinv_kernel() {
    int i = blockIdx.x * blockDim.x + threadIdx.x;
    if (i >= NBc) return;
    int d = g_deg[i];
    g_dinv[i] = (d > 0) ? (1.0f / sqrtf((float)d)) : 0.0f;
}

// ---------------- Tx1: deterministic gather-side aggregation ----------------
// dst = q*N + n receives only from center rows (b', n) with b' in {q-1, q}
// whose edge index i has count(i)==q (linspace-count structure).
__global__ void tx1_kernel() {
    int flat = blockIdx.x * blockDim.x + threadIdx.x;
    if (flat >= NBc * Cc) return;
    int d  = flat / Cc, ch = flat % Cc;
    int q  = d >> 12, n = d & (Nn - 1);
    float dv = g_dinv[d];
    float acc = 0.f;
#pragma unroll
    for (int bb = 0; bb < 2; bb++) {
        int bp = q - 1 + bb;
        if (bp < 0 || bp >= Bc) continue;
        int ibase = (bp * Nn + n) * KK;
#pragma unroll
        for (int j = 0; j < KK; j++) {
            int i = ibase + j;
            if (edge_count(i) == q) {
                int src = g_nn[i] + q * Nn;   // always < NB since q <= 7
                acc = fmaf(-dv * g_dinv[src], g_nodes[src * Cc + ch], acc);
            }
        }
    }
    g_tx1[flat] = acc;
}

// ---------------- epilogue: out = nodes@W0 + Tx1@W1 + bias ----------------
__global__ void out_kernel(const float* __restrict__ W0, const float* __restrict__ W1,
                           const float* __restrict__ bias, float* __restrict__ out) {
    __shared__ float sW0[Cc * Cc], sW1[Cc * Cc], sb[Cc];
    int t = threadIdx.x;
    for (int i = t; i < Cc * Cc; i += blockDim.x) { sW0[i] = W0[i]; sW1[i] = W1[i]; }
    if (t < Cc) sb[t] = bias[t];
    __syncthreads();
    int flat = blockIdx.x * blockDim.x + t;
    if (flat >= NBc * Cc) return;
    int d = flat / Cc, co = flat % Cc;
    const float* nrow = &g_nodes[d * Cc];
    const float* trow = &g_tx1[d * Cc];
    float acc = sb[co];
#pragma unroll
    for (int k = 0; k < Cc; k++)
        acc = fmaf(nrow[k], sW0[k * Cc + co], fmaf(trow[k], sW1[k * Cc + co], acc));
    out[flat] = acc;
}

// ---------------- launch ----------------
extern "C" void kernel_launch(void* const* d_in, const int* in_sizes, int n_in,
                              void* d_out, int out_size) {
    const float* x    = (const float*)d_in[0];
    const float* W0   = (const float*)d_in[1];
    const float* W1   = (const float*)d_in[2];
    const float* bias = (const float*)d_in[3];
    float* out = (float*)d_out;
    (void)in_sizes; (void)n_in; (void)out_size;

    prep_kernel<<<NBc / 256, 256>>>(x);
    dim3 gknn(Nn / QT, Bc);
    knn_kernel<<<gknn, 256>>>();
    deg_kernel<<<(Ec + 255) / 256, 256>>>();
    dinv_kernel<<<NBc / 256, 256>>>();
    tx1_kernel<<<(NBc * Cc) / 256, 256>>>();
    out_kernel<<<(NBc * Cc) / 256, 256>>>(W0, W1, bias, out);
}

// round 7
// speedup vs baseline: 2.4609x; 1.0260x over previous
#include <cuda_runtime.h>
#include <math.h>

#define Bc   8
#define Cc   48
#define Nn   4096
#define KK   9
#define NBc  32768          // B*N
#define Ec   (Bc*Nn*KK)     // 294912

// -------- scratch (static device globals; no allocation) --------
__device__ float g_xnT[Bc*Cc*Nn];   // normalized features, CHANNEL-major [b][c][n]
__device__ float g_nodes[NBc*Cc];   // raw features, node-major
__device__ float g_sq[NBc];         // sum of squares of normalized row
__device__ int   g_nn[NBc*KK];      // knn indices (within batch, 0..N-1)
__device__ int   g_deg[NBc];
__device__ float g_dinv[NBc];
__device__ float g_tx1[NBc*Cc];

// faithful replication of jnp.linspace(0, 8, E).astype(int32):
// value_i = fl(fl(i) * fl(8/294911)), truncated toward zero.
__device__ __forceinline__ int edge_count(int i) {
    const float STEP = 8.0f / 294911.0f;
    return (int)((float)i * STEP);
}

// monotone float->uint map: preserves < ordering for all finite floats
__device__ __forceinline__ unsigned int fmono(float d) {
    unsigned int u = __float_as_uint(d);
    return (u & 0x80000000u) ? ~u : (u | 0x80000000u);
}
__device__ __forceinline__ float fmono_inv(unsigned int u) {
    return __uint_as_float((u & 0x80000000u) ? (u ^ 0x80000000u) : ~u);
}

// packed f32x2 helpers (element-wise IEEE fp32: bit-identical to 2x fmaf)
__device__ __forceinline__ unsigned long long pack_dup(float v) {
    unsigned long long r;
    asm("mov.b64 %0, {%1, %1};" : "=l"(r) : "r"(__float_as_uint(v)));
    return r;
}
__device__ __forceinline__ void fma2(unsigned long long& acc,
                                     unsigned long long a, unsigned long long b) {
    asm("fma.rn.f32x2 %0, %1, %2, %0;" : "+l"(acc) : "l"(a), "l"(b));
}
__device__ __forceinline__ void unpack2(unsigned long long p, float& lo, float& hi) {
    unsigned int l, h;
    asm("mov.b64 {%0, %1}, %2;" : "=r"(l), "=r"(h) : "l"(p));
    lo = __uint_as_float(l); hi = __uint_as_float(h);
}

// ---------------- prep: normalize; emit channel-major + node-major ----------------
__global__ void prep_kernel(const float* __restrict__ x) {
    int node = blockIdx.x * blockDim.x + threadIdx.x;
    if (node >= NBc) return;
    int b = node >> 12, n = node & (Nn - 1);
    const float* xb = x + (size_t)b * Cc * Nn + n;
    float v[Cc];
    float ss = 0.f;
#pragma unroll
    for (int c = 0; c < Cc; c++) { v[c] = xb[c * Nn]; ss += v[c] * v[c]; }
    float m = fmaxf(sqrtf(ss), 1e-12f);
    float sq = 0.f;
    float* xT = g_xnT + (size_t)b * Cc * Nn + n;
#pragma unroll
    for (int c = 0; c < Cc; c++) {
        float xv = v[c] / m;
        xT[c * Nn]             = xv;   // channel-major (coalesced across threads)
        g_nodes[node * Cc + c] = v[c];
        sq += xv * xv;
    }
    g_sq[node]  = sq;
    g_deg[node] = 0;
}

// ---------------- KNN: tiled distances + fused top-9 (u64 reg lists) ----------------
// Block 256: each thread owns 1 query row x 16 cand cols.
// ms tiles granule-permuted so each m LDS.128 hits one contiguous 64B window.
// Inner product uses packed fma.rn.f32x2 (8 FFMA2/k instead of 16 FFMA).
#define QT 64
#define MT 64

__global__ __launch_bounds__(256, 4) void knn_kernel() {
    __shared__ float qs[Cc * QT];        // [k*64 + r]                (12 KB)
    __shared__ float ms[2][Cc * MT];     // [k*64 + perm(c)] ping-pong (24 KB)
    __shared__ float sqm[2][MT];

    int t    = threadIdx.x;
    int row  = t >> 2;            // 0..63
    int cs   = t & 3;             // column segment 0..3
    int cseg = cs * 16;
    int b    = blockIdx.y;
    int qBase = blockIdx.x * QT;
    int nodeBase = b * Nn;
    const float* xT = g_xnT + (size_t)b * Cc * Nn;

    // qs: straight coalesced copy (already k-major)
    for (int i = t; i < Cc * 16; i += 256) {
        int k = i >> 4, c4 = i & 15;
        *(float4*)&qs[k * QT + c4 * 4] =
            *(const float4*)&xT[k * Nn + qBase + c4 * 4];
    }
    // preload tile 0 with granule permutation:
    // source float4 #c4 (cols c4*4..c4*4+3) -> dest float offset (c4&3)*16+(c4>>2)*4
    for (int i = t; i < Cc * 16; i += 256) {
        int k = i >> 4, c4 = i & 15;
        int dp = ((c4 & 3) << 4) + ((c4 >> 2) << 2);
        *(float4*)&ms[0][k * MT + dp] =
            *(const float4*)&xT[k * Nn + c4 * 4];
    }
    if (t < MT) sqm[0][t] = g_sq[nodeBase + t];
    float sqq = g_sq[nodeBase + qBase + row];

    // sentinel: (d=+INF, idx=0xFFFFFFFF)
    unsigned long long lst[KK];
#pragma unroll
    for (int s = 0; s < KK; s++) lst[s] = 0xFF800000FFFFFFFFULL;
    float thr = __int_as_float(0x7F800000);   // +INF

    __syncthreads();

    int p = 0;
    for (int mb = 0; mb < Nn; mb += MT) {
        // prefetch next tile into the other buffer
        if (mb + MT < Nn) {
            for (int i = t; i < Cc * 16; i += 256) {
                int k = i >> 4, c4 = i & 15;
                int dp = ((c4 & 3) << 4) + ((c4 >> 2) << 2);
                *(float4*)&ms[1 - p][k * MT + dp] =
                    *(const float4*)&xT[k * Nn + (mb + MT) + c4 * 4];
            }
            if (t < MT) sqm[1 - p][t] = g_sq[nodeBase + mb + MT + t];
        }

        const float* msp = ms[p];
        unsigned long long accp[8];      // 8 packed f32x2 accumulators = 16 cols
#pragma unroll
        for (int j = 0; j < 8; j++) accp[j] = 0ULL;

#pragma unroll 8
        for (int k = 0; k < Cc; k++) {
            unsigned long long qq = pack_dup(qs[k * QT + row]);
            const unsigned long long* mrow =
                (const unsigned long long*)&msp[k * MT + cs * 4];
            // granule g at float offset g*16 + cs*4 -> cols cseg+4g..cseg+4g+3
            // as u64 pairs: mrow[0..1] (g0), mrow[8..9] (g1), mrow[16..17] (g2), mrow[24..25] (g3)
            fma2(accp[0], qq, mrow[0]);  fma2(accp[1], qq, mrow[1]);
            fma2(accp[2], qq, mrow[8]);  fma2(accp[3], qq, mrow[9]);
            fma2(accp[4], qq, mrow[16]); fma2(accp[5], qq, mrow[17]);
            fma2(accp[6], qq, mrow[24]); fma2(accp[7], qq, mrow[25]);
        }

        float acc[16];
#pragma unroll
        for (int j = 0; j < 8; j++) unpack2(accp[j], acc[2 * j], acc[2 * j + 1]);

#pragma unroll
        for (int j = 0; j < 16; j++) {
            float d = (sqq + sqm[p][cseg + j]) - 2.f * acc[j];
            if (d <= thr) {
                int mi = mb + cseg + j;
                unsigned long long key =
                    ((unsigned long long)fmono(d) << 32) | (unsigned int)mi;
                if (key < lst[KK - 1]) {
                    lst[KK - 1] = key;
#pragma unroll
                    for (int s = KK - 1; s > 0; --s) {
                        if (lst[s] < lst[s - 1]) {
                            unsigned long long tmp = lst[s];
                            lst[s] = lst[s - 1]; lst[s - 1] = tmp;
                        }
                    }
                    thr = fmono_inv((unsigned int)(lst[KK - 1] >> 32));
                }
            }
        }

        __syncthreads();
        p ^= 1;
    }

    // butterfly merge across the 4 threads (quad) sharing this query row
#pragma unroll
    for (int delta = 1; delta <= 2; delta <<= 1) {
        unsigned long long other[KK];
#pragma unroll
        for (int s = 0; s < KK; s++)
            other[s] = __shfl_xor_sync(0xffffffffu, lst[s], delta);
#pragma unroll
        for (int s = 0; s < KK; s++) {
            if (other[s] < lst[KK - 1]) {
                lst[KK - 1] = other[s];
#pragma unroll
                for (int s2 = KK - 1; s2 > 0; --s2) {
                    if (lst[s2] < lst[s2 - 1]) {
                        unsigned long long tmp = lst[s2];
                        lst[s2] = lst[s2 - 1]; lst[s2 - 1] = tmp;
                    }
                }
            }
        }
    }

    if ((t & 3) == 0) {
        int nrow = nodeBase + qBase + row;
#pragma unroll
        for (int s = 0; s < KK; s++)
            g_nn[nrow * KK + s] = (int)(unsigned int)(lst[s] & 0xFFFFFFFFu);
    }
}

// ---------------- degree (int atomics: deterministic) ----------------
__global__ void deg_kernel() {
    int i = blockIdx.x * blockDim.x + threadIdx.x;
    if (i >= Ec) return;
    int cnt  = edge_count(i);
    int rown = i / KK;              // b*N + n
    int n    = rown & (Nn - 1);
    int m    = g_nn[i];
    int src  = m + cnt * Nn;
    int dst  = n + cnt * Nn;
    if (src < NBc && dst < NBc) atomicAdd(&g_deg[src], 1);
}

__global__ void dinv_kernel() {
    int i = blockIdx.x * blockDim.x + threadIdx.x;
    if (i >= NBc) return;
    int d = g_deg[i];
    g_dinv[i] = (d > 0) ? (1.0f / sqrtf((float)d)) : 0.0f;
}

// ---------------- Tx1: deterministic gather-side aggregation ----------------
// dst = q*N + n receives only from center rows (b', n) with b' in {q-1, q}
// whose edge index i has count(i)==q (linspace-count structure).
__global__ void tx1_kernel() {
    int flat = blockIdx.x * blockDim.x + threadIdx.x;
    if (flat >= NBc * Cc) return;
    int d  = flat / Cc, ch = flat % Cc;
    int q  = d >> 12, n = d & (Nn - 1);
    float dv = g_dinv[d];
    float acc = 0.f;
#pragma unroll
    for (int bb = 0; bb < 2; bb++) {
        int bp = q - 1 + bb;
        if (bp < 0 || bp >= Bc) continue;
        int ibase = (bp * Nn + n) * KK;
#pragma unroll
        for (int j = 0; j < KK; j++) {
            int i = ibase + j;
            if (edge_count(i) == q) {
                int src = g_nn[i] + q * Nn;   // always < NB since q <= 7
                acc = fmaf(-dv * g_dinv[src], g_nodes[src * Cc + ch], acc);
            }
        }
    }
    g_tx1[flat] = acc;
}

// ---------------- epilogue: out = nodes@W0 + Tx1@W1 + bias ----------------
__global__ void out_kernel(const float* __restrict__ W0, const float* __restrict__ W1,
                           const float* __restrict__ bias, float* __restrict__ out) {
    __shared__ float sW0[Cc * Cc], sW1[Cc * Cc], sb[Cc];
    int t = threadIdx.x;
    for (int i = t; i < Cc * Cc; i += blockDim.x) { sW0[i] = W0[i]; sW1[i] = W1[i]; }
    if (t < Cc) sb[t] = bias[t];
    __syncthreads();
    int flat = blockIdx.x * blockDim.x + t;
    if (flat >= NBc * Cc) return;
    int d = flat / Cc, co = flat % Cc;
    const float* nrow = &g_nodes[d * Cc];
    const float* trow = &g_tx1[d * Cc];
    float acc = sb[co];
#pragma unroll
    for (int k = 0; k < Cc; k++)
        acc = fmaf(nrow[k], sW0[k * Cc + co], fmaf(trow[k], sW1[k * Cc + co], acc));
    out[flat] = acc;
}

// ---------------- launch ----------------
extern "C" void kernel_launch(void* const* d_in, const int* in_sizes, int n_in,
                              void* d_out, int out_size) {
    const float* x    = (const float*)d_in[0];
    const float* W0   = (const float*)d_in[1];
    const float* W1   = (const float*)d_in[2];
    const float* bias = (const float*)d_in[3];
    float* out = (float*)d_out;
    (void)in_sizes; (void)n_in; (void)out_size;

    prep_kernel<<<NBc / 256, 256>>>(x);
    dim3 gknn(Nn / QT, Bc);
    knn_kernel<<<gknn, 256>>>();
    deg_kernel<<<(Ec + 255) / 256, 256>>>();
    dinv_kernel<<<NBc / 256, 256>>>();
    tx1_kernel<<<(NBc * Cc) / 256, 256>>>();
    out_kernel<<<(NBc * Cc) / 256, 256>>>(W0, W1, bias, out);
}

// round 9
// speedup vs baseline: 3.1214x; 1.2684x over previous
#include <cuda_runtime.h>
#include <math.h>

#define Bc   8
#define Cc   48
#define Nn   4096
#define KK   9
#define NBc  32768          // B*N
#define Ec   (Bc*Nn*KK)     // 294912

// -------- scratch (static device globals; no allocation) --------
__device__ float g_xnT[Bc*Cc*Nn];   // normalized features, CHANNEL-major [b][c][n]
__device__ float g_nodes[NBc*Cc];   // raw features, node-major
__device__ float g_sq[NBc];         // sum of squares of normalized row
__device__ int   g_nn[NBc*KK];      // knn indices (within batch, 0..N-1)
__device__ int   g_deg[NBc];
__device__ float g_dinv[NBc];
__device__ float g_tx1[NBc*Cc];

// faithful replication of jnp.linspace(0, 8, E).astype(int32):
// value_i = fl(fl(i) * fl(8/294911)), truncated toward zero.
__device__ __forceinline__ int edge_count(int i) {
    const float STEP = 8.0f / 294911.0f;
    return (int)((float)i * STEP);
}

// monotone float->uint map: preserves < ordering for all finite floats
__device__ __forceinline__ unsigned int fmono(float d) {
    unsigned int u = __float_as_uint(d);
    return (u & 0x80000000u) ? ~u : (u | 0x80000000u);
}
__device__ __forceinline__ float fmono_inv(unsigned int u) {
    return __uint_as_float((u & 0x80000000u) ? (u ^ 0x80000000u) : ~u);
}

// packed f32x2 helpers (element-wise IEEE fp32: bit-identical to 2x fmaf)
__device__ __forceinline__ unsigned long long pack_dup(float v) {
    unsigned long long r;
    asm("mov.b64 %0, {%1, %1};" : "=l"(r) : "r"(__float_as_uint(v)));
    return r;
}
__device__ __forceinline__ void fma2(unsigned long long& acc,
                                     unsigned long long a, unsigned long long b) {
    asm("fma.rn.f32x2 %0, %1, %2, %0;" : "+l"(acc) : "l"(a), "l"(b));
}
__device__ __forceinline__ void unpack2(unsigned long long p, float& lo, float& hi) {
    unsigned int l, h;
    asm("mov.b64 {%0, %1}, %2;" : "=r"(l), "=r"(h) : "l"(p));
    lo = __uint_as_float(l); hi = __uint_as_float(h);
}

// ---------------- prep: normalize; emit channel-major + node-major ----------------
__global__ void prep_kernel(const float* __restrict__ x) {
    int node = blockIdx.x * blockDim.x + threadIdx.x;
    if (node >= NBc) return;
    int b = node >> 12, n = node & (Nn - 1);
    const float* xb = x + (size_t)b * Cc * Nn + n;
    float v[Cc];
    float ss = 0.f;
#pragma unroll
    for (int c = 0; c < Cc; c++) { v[c] = xb[c * Nn]; ss += v[c] * v[c]; }
    float m = fmaxf(sqrtf(ss), 1e-12f);
    float sq = 0.f;
    float* xT = g_xnT + (size_t)b * Cc * Nn + n;
#pragma unroll
    for (int c = 0; c < Cc; c++) {
        float xv = v[c] / m;
        xT[c * Nn]             = xv;   // channel-major (coalesced across threads)
        g_nodes[node * Cc + c] = v[c];
        sq += xv * xv;
    }
    g_sq[node]  = sq;
    g_deg[node] = 0;
}

// ---------------- KNN: tiled distances + fused top-9 (u64 reg lists) ----------------
// Block 256: each thread owns 2 query rows x 16 cand cols (QT=128, MT=64).
// ms tiles granule-permuted so each m LDS.128 hits one contiguous 64B window.
// Inner product uses packed fma.rn.f32x2.
#define QT 128
#define MT 64

__global__ __launch_bounds__(256, 2) void knn_kernel() {
    __shared__ float qs[Cc * QT];        // [k*128 + r]                (24 KB)
    __shared__ float ms[2][Cc * MT];     // [k*64 + perm(c)] ping-pong (24 KB)
    __shared__ float sqm[2][MT];

    int t    = threadIdx.x;
    int r0   = (t >> 2) * 2;      // 0,2,...,126
    int cs   = t & 3;             // column segment 0..3
    int cseg = cs * 16;
    int b    = blockIdx.y;
    int qBase = blockIdx.x * QT;
    int nodeBase = b * Nn;
    const float* xT = g_xnT + (size_t)b * Cc * Nn;

    // qs: straight coalesced copy (already k-major). Cc*QT/4 = 1536 float4s.
    for (int i = t; i < Cc * 32; i += 256) {
        int k = i >> 5, c4 = i & 31;
        *(float4*)&qs[k * QT + c4 * 4] =
            *(const float4*)&xT[k * Nn + qBase + c4 * 4];
    }
    // preload tile 0 with granule permutation:
    // source float4 #c4 (cols c4*4..c4*4+3) -> dest float offset (c4&3)*16+(c4>>2)*4
    for (int i = t; i < Cc * 16; i += 256) {
        int k = i >> 4, c4 = i & 15;
        int dp = ((c4 & 3) << 4) + ((c4 >> 2) << 2);
        *(float4*)&ms[0][k * MT + dp] =
            *(const float4*)&xT[k * Nn + c4 * 4];
    }
    if (t < MT) sqm[0][t] = g_sq[nodeBase + t];
    float sqq0 = g_sq[nodeBase + qBase + r0];
    float sqq1 = g_sq[nodeBase + qBase + r0 + 1];

    // sentinel: (d=+INF, idx=0xFFFFFFFF)
    unsigned long long lst0[KK], lst1[KK];
#pragma unroll
    for (int s = 0; s < KK; s++) { lst0[s] = 0xFF800000FFFFFFFFULL; lst1[s] = 0xFF800000FFFFFFFFULL; }
    float thr0 = __int_as_float(0x7F800000);
    float thr1 = __int_as_float(0x7F800000);

    __syncthreads();

    int p = 0;
    for (int mb = 0; mb < Nn; mb += MT) {
        // prefetch next tile into the other buffer
        if (mb + MT < Nn) {
            for (int i = t; i < Cc * 16; i += 256) {
                int k = i >> 4, c4 = i & 15;
                int dp = ((c4 & 3) << 4) + ((c4 >> 2) << 2);
                *(float4*)&ms[1 - p][k * MT + dp] =
                    *(const float4*)&xT[k * Nn + (mb + MT) + c4 * 4];
            }
            if (t < MT) sqm[1 - p][t] = g_sq[nodeBase + mb + MT + t];
        }

        const float* msp = ms[p];
        unsigned long long a0[8], a1[8];   // packed f32x2 accumulators, per row
#pragma unroll
        for (int j = 0; j < 8; j++) { a0[j] = 0ULL; a1[j] = 0ULL; }

#pragma unroll 6
        for (int k = 0; k < Cc; k++) {
            float2 q2 = *(const float2*)&qs[k * QT + r0];     // rows r0, r0+1
            unsigned long long qqa = pack_dup(q2.x);
            unsigned long long qqb = pack_dup(q2.y);
            const unsigned long long* mrow =
                (const unsigned long long*)&msp[k * MT + cs * 4];
            unsigned long long m0 = mrow[0],  m1 = mrow[1];
            unsigned long long m2 = mrow[8],  m3 = mrow[9];
            unsigned long long m4 = mrow[16], m5 = mrow[17];
            unsigned long long m6 = mrow[24], m7 = mrow[25];
            fma2(a0[0], qqa, m0); fma2(a0[1], qqa, m1);
            fma2(a0[2], qqa, m2); fma2(a0[3], qqa, m3);
            fma2(a0[4], qqa, m4); fma2(a0[5], qqa, m5);
            fma2(a0[6], qqa, m6); fma2(a0[7], qqa, m7);
            fma2(a1[0], qqb, m0); fma2(a1[1], qqb, m1);
            fma2(a1[2], qqb, m2); fma2(a1[3], qqb, m3);
            fma2(a1[4], qqb, m4); fma2(a1[5], qqb, m5);
            fma2(a1[6], qqb, m6); fma2(a1[7], qqb, m7);
        }

        float acc0[16], acc1[16];
#pragma unroll
        for (int j = 0; j < 8; j++) {
            unpack2(a0[j], acc0[2 * j], acc0[2 * j + 1]);
            unpack2(a1[j], acc1[2 * j], acc1[2 * j + 1]);
        }

#pragma unroll
        for (int j = 0; j < 16; j++) {
            float sm = sqm[p][cseg + j];
            int   mi = mb + cseg + j;
            float d0 = (sqq0 + sm) - 2.f * acc0[j];
            if (d0 <= thr0) {
                unsigned long long key =
                    ((unsigned long long)fmono(d0) << 32) | (unsigned int)mi;
                if (key < lst0[KK - 1]) {
                    lst0[KK - 1] = key;
#pragma unroll
                    for (int s = KK - 1; s > 0; --s) {
                        if (lst0[s] < lst0[s - 1]) {
                            unsigned long long tmp = lst0[s];
                            lst0[s] = lst0[s - 1]; lst0[s - 1] = tmp;
                        }
                    }
                    thr0 = fmono_inv((unsigned int)(lst0[KK - 1] >> 32));
                }
            }
            float d1 = (sqq1 + sm) - 2.f * acc1[j];
            if (d1 <= thr1) {
                unsigned long long key =
                    ((unsigned long long)fmono(d1) << 32) | (unsigned int)mi;
                if (key < lst1[KK - 1]) {
                    lst1[KK - 1] = key;
#pragma unroll
                    for (int s = KK - 1; s > 0; --s) {
                        if (lst1[s] < lst1[s - 1]) {
                            unsigned long long tmp = lst1[s];
                            lst1[s] = lst1[s - 1]; lst1[s - 1] = tmp;
                        }
                    }
                    thr1 = fmono_inv((unsigned int)(lst1[KK - 1] >> 32));
                }
            }
        }

        __syncthreads();
        p ^= 1;
    }

    // butterfly merge across the 4 threads (quad) sharing this row pair
#pragma unroll
    for (int delta = 1; delta <= 2; delta <<= 1) {
        unsigned long long o0[KK], o1[KK];
#pragma unroll
        for (int s = 0; s < KK; s++) {
            o0[s] = __shfl_xor_sync(0xffffffffu, lst0[s], delta);
            o1[s] = __shfl_xor_sync(0xffffffffu, lst1[s], delta);
        }
#pragma unroll
        for (int s = 0; s < KK; s++) {
            if (o0[s] < lst0[KK - 1]) {
                lst0[KK - 1] = o0[s];
#pragma unroll
                for (int s2 = KK - 1; s2 > 0; --s2) {
                    if (lst0[s2] < lst0[s2 - 1]) {
                        unsigned long long tmp = lst0[s2];
                        lst0[s2] = lst0[s2 - 1]; lst0[s2 - 1] = tmp;
                    }
                }
            }
            if (o1[s] < lst1[KK - 1]) {
                lst1[KK - 1] = o1[s];
#pragma unroll
                for (int s2 = KK - 1; s2 > 0; --s2) {
                    if (lst1[s2] < lst1[s2 - 1]) {
                        unsigned long long tmp = lst1[s2];
                        lst1[s2] = lst1[s2 - 1]; lst1[s2 - 1] = tmp;
                    }
                }
            }
        }
    }

    if ((t & 3) == 0) {
        int nrow = nodeBase + qBase + r0;
#pragma unroll
        for (int s = 0; s < KK; s++) {
            g_nn[nrow * KK + s]        = (int)(unsigned int)(lst0[s] & 0xFFFFFFFFu);
            g_nn[(nrow + 1) * KK + s]  = (int)(unsigned int)(lst1[s] & 0xFFFFFFFFu);
        }
    }
}

// ---------------- degree (int atomics: deterministic) ----------------
__global__ void deg_kernel() {
    int i = blockIdx.x * blockDim.x + threadIdx.x;
    if (i >= Ec) return;
    int cnt  = edge_count(i);
    int rown = i / KK;              // b*N + n
    int n    = rown & (Nn - 1);
    int m    = g_nn[i];
    int src  = m + cnt * Nn;
    int dst  = n + cnt * Nn;
    if (src < NBc && dst < NBc) atomicAdd(&g_deg[src], 1);
}

__global__ void dinv_kernel() {
    int i = blockIdx.x * blockDim.x + threadIdx.x;
    if (i >= NBc) return;
    int d = g_deg[i];
    g_dinv[i] = (d > 0) ? (1.0f / sqrtf((float)d)) : 0.0f;
}

// ---------------- Tx1: deterministic gather-side aggregation ----------------
// dst = q*N + n receives only from center rows (b', n) with b' in {q-1, q}
// whose edge index i has count(i)==q (linspace-count structure).
__global__ void tx1_kernel() {
    int flat = blockIdx.x * blockDim.x + threadIdx.x;
    if (flat >= NBc * Cc) return;
    int d  = flat / Cc, ch = flat % Cc;
    int q  = d >> 12, n = d & (Nn - 1);
    float dv = g_dinv[d];
    float acc = 0.f;
#pragma unroll
    for (int bb = 0; bb < 2; bb++) {
        int bp = q - 1 + bb;
        if (bp < 0 || bp >= Bc) continue;
        int ibase = (bp * Nn + n) * KK;
#pragma unroll
        for (int j = 0; j < KK; j++) {
            int i = ibase + j;
            if (edge_count(i) == q) {
                int src = g_nn[i] + q * Nn;   // always < NB since q <= 7
                acc = fmaf(-dv * g_dinv[src], g_nodes[src * Cc + ch], acc);
            }
        }
    }
    g_tx1[flat] = acc;
}

// ---------------- epilogue: out = nodes@W0 + Tx1@W1 + bias ----------------
__global__ void out_kernel(const float* __restrict__ W0, const float* __restrict__ W1,
                           const float* __restrict__ bias, float* __restrict__ out) {
    __shared__ float sW0[Cc * Cc], sW1[Cc * Cc], sb[Cc];
    int t = threadIdx.x;
    for (int i = t; i < Cc * Cc; i += blockDim.x) { sW0[i] = W0[i]; sW1[i] = W1[i]; }
    if (t < Cc) sb[t] = bias[t];
    __syncthreads();
    int flat = blockIdx.x * blockDim.x + t;
    if (flat >= NBc * Cc) return;
    int d = flat / Cc, co = flat % Cc;
    const float* nrow = &g_nodes[d * Cc];
    const float* trow = &g_tx1[d * Cc];
    float acc = sb[co];
#pragma unroll
    for (int k = 0; k < Cc; k++)
        acc = fmaf(nrow[k], sW0[k * Cc + co], fmaf(trow[k], sW1[k * Cc + co], acc));
    out[flat] = acc;
}

// ---------------- launch ----------------
extern "C" void kernel_launch(void* const* d_in, const int* in_sizes, int n_in,
                              void* d_out, int out_size) {
    const float* x    = (const float*)d_in[0];
    const float* W0   = (const float*)d_in[1];
    const float* W1   = (const float*)d_in[2];
    const float* bias = (const float*)d_in[3];
    float* out = (float*)d_out;
    (void)in_sizes; (void)n_in; (void)out_size;

    prep_kernel<<<NBc / 256, 256>>>(x);
    dim3 gknn(Nn / QT, Bc);
    knn_kernel<<<gknn, 256>>>();
    deg_kernel<<<(Ec + 255) / 256, 256>>>();
    dinv_kernel<<<NBc / 256, 256>>>();
    tx1_kernel<<<(NBc * Cc) / 256, 256>>>();
    out_kernel<<<(NBc * Cc) / 256, 256>>>(W0, W1, bias, out);
}